// round 12
// baseline (speedup 1.0000x reference)
#include <cuda_runtime.h>
#include <cstdint>
#include <cstddef>

#define TT 512
#define BB 64
#define NCTA 64

// ---------------- static scratch ----------------
__device__ float g_seqA[(size_t)TT * BB * 512];   // layer-output sequence (T,B,H)
__device__ float g_seqB[(size_t)TT * BB * 512];
__device__ float g_G[(size_t)TT * BB * 2048];     // precomputed input gates (T*B, 4H)
__device__ float g_hbuf[2][BB * 512];             // recurrent h: PERMUTED tf32 fragment layout
__device__ float g_hTp[BB * 512];                 // encoder final h (permuted tf32)
__device__ float g_cT[BB * 512];                  // encoder final c (full precision)
__device__ int g_fl[NCTA];                        // per-CTA monotonic step flags
__device__ int g_barCount;
__device__ volatile int g_barGen;

// ---------------- helpers ----------------
__device__ __forceinline__ uint32_t f2tf32(float f) {
    uint32_t u;
    asm("cvt.rna.tf32.f32 %0, %1;" : "=r"(u) : "f"(f));
    return u;
}

__device__ __forceinline__ void mma_tf32(float c[4], uint32_t a0, uint32_t a1,
                                         uint32_t a2, uint32_t a3,
                                         uint32_t b0, uint32_t b1) {
    asm volatile(
        "mma.sync.aligned.m16n8k8.row.col.f32.tf32.tf32.f32 "
        "{%0,%1,%2,%3}, {%4,%5,%6,%7}, {%8,%9}, {%0,%1,%2,%3};"
        : "+f"(c[0]), "+f"(c[1]), "+f"(c[2]), "+f"(c[3])
        : "r"(a0), "r"(a1), "r"(a2), "r"(a3), "r"(b0), "r"(b1));
}

__device__ __forceinline__ float sigf(float x) { return 1.0f / (1.0f + __expf(-x)); }

__device__ __forceinline__ uint32_t smem_u32(const void* p) {
    uint32_t a;
    asm("{ .reg .u64 t; cvta.to.shared.u64 t, %1; cvt.u32.u64 %0, t; }" : "=r"(a) : "l"(p));
    return a;
}

__device__ __forceinline__ void cpa16(uint32_t s, const void* g) {
    asm volatile("cp.async.cg.shared.global [%0], [%1], 16;" :: "r"(s), "l"(g) : "memory");
}
__device__ __forceinline__ void cp_commit() { asm volatile("cp.async.commit_group;" ::: "memory"); }
template <int N>
__device__ __forceinline__ void cp_waitg() { asm volatile("cp.async.wait_group %0;" :: "n"(N) : "memory"); }

// legacy atomic barrier (replay-safe) — used ONCE per launch after init/reset
__device__ __forceinline__ void atomic_bar() {
    __threadfence();
    __syncthreads();
    if (threadIdx.x == 0) {
        int g = g_barGen;
        if (atomicAdd(&g_barCount, 1) == NCTA - 1) {
            g_barCount = 0;
            __threadfence();
            g_barGen = g + 1;
        } else {
            while (g_barGen == g) { __nanosleep(64); }
        }
        __threadfence();
    }
    __syncthreads();
}

// wait until the 16 producer CTAs of group g have posted flag >= t.
// Tight spin (fast wake); rare nanosleep fallback for pathological scheduling.
__device__ __forceinline__ void wait_group_flags(int g, int t) {
    if (threadIdx.x < 16) {
        const int* f = &g_fl[g * 16 + threadIdx.x];
        int v, spins = 0;
        for (;;) {
            asm volatile("ld.acquire.gpu.b32 %0, [%1];" : "=r"(v) : "l"(f) : "memory");
            if (v >= t) break;
            if (++spins > (1 << 14)) { __nanosleep(64); spins = 0; }
        }
    }
    __syncthreads();
}

// ---------------- input GEMM: G = src @ W^T + b1 + b2 --------------------------
// Register double-buffered: prefetch next K-tile to regs while mma-ing current
// SMEM tile; STS after all reads.
__global__ void __launch_bounds__(256) gemm_input(int srcSel,
                                                  const float* __restrict__ xin,
                                                  const float* __restrict__ W,
                                                  const float* __restrict__ b1,
                                                  const float* __restrict__ b2,
                                                  int Kdim, int Ndim, int rev) {
    __shared__ __align__(16) uint32_t As[128][36];
    __shared__ __align__(16) uint32_t Bs[128][36];

    const float* __restrict__ S = (srcSel == 0) ? xin : (srcSel == 1) ? g_seqA : g_seqB;

    int tid = threadIdx.x;
    int wid = tid >> 5, lane = tid & 31, l4 = lane >> 2, tig = lane & 3;
    int wr = wid >> 2, wc = wid & 3;
    int m0 = blockIdx.y * 128, n0 = blockIdx.x * 128;

    size_t aoff[4];
    const float* wrow[4];
#pragma unroll
    for (int i = 0; i < 4; i++) {
        int v = tid + i * 256;
        int row = v >> 3, kv = v & 7;
        int m = m0 + row;
        size_t off;
        if (srcSel == 0) {
            int t = m >> 6;
            if (rev) t = TT - 1 - t;
            off = ((size_t)(m & 63) * TT + t) * Kdim;
        } else {
            off = (size_t)m * Kdim;
        }
        aoff[i] = off + kv * 4;
        wrow[i] = W + (size_t)(n0 + row) * Kdim + kv * 4;
    }

    float acc[4][4][4];
#pragma unroll
    for (int fm = 0; fm < 4; fm++)
#pragma unroll
        for (int fn = 0; fn < 4; fn++)
#pragma unroll
            for (int i = 0; i < 4; i++) acc[fm][fn][i] = 0.0f;

    float4 ra[4], rb[4];
#pragma unroll
    for (int i = 0; i < 4; i++) {
        ra[i] = *(const float4*)(S + aoff[i]);
        rb[i] = *(const float4*)(wrow[i]);
    }

    for (int kt = 0; kt < Kdim; kt += 32) {
#pragma unroll
        for (int i = 0; i < 4; i++) {
            int v = tid + i * 256;
            int row = v >> 3, kv = v & 7;
            uint4 ua, ub;
            ua.x = f2tf32(ra[i].x); ua.y = f2tf32(ra[i].y);
            ua.z = f2tf32(ra[i].z); ua.w = f2tf32(ra[i].w);
            ub.x = f2tf32(rb[i].x); ub.y = f2tf32(rb[i].y);
            ub.z = f2tf32(rb[i].z); ub.w = f2tf32(rb[i].w);
            *(uint4*)&As[row][kv * 4] = ua;
            *(uint4*)&Bs[row][kv * 4] = ub;
        }
        __syncthreads();

        if (kt + 32 < Kdim) {
#pragma unroll
            for (int i = 0; i < 4; i++) {
                ra[i] = *(const float4*)(S + aoff[i] + kt + 32);
                rb[i] = *(const float4*)(wrow[i] + kt + 32);
            }
        }

#pragma unroll
        for (int ks = 0; ks < 4; ks++) {
            const int k = ks * 8;
            uint32_t af[4][4], bf[4][2];
#pragma unroll
            for (int fm = 0; fm < 4; fm++) {
                int r = wr * 64 + fm * 16 + l4;
                af[fm][0] = As[r][k + tig];
                af[fm][1] = As[r + 8][k + tig];
                af[fm][2] = As[r][k + tig + 4];
                af[fm][3] = As[r + 8][k + tig + 4];
            }
#pragma unroll
            for (int fn = 0; fn < 4; fn++) {
                int c = wc * 32 + fn * 8 + l4;
                bf[fn][0] = Bs[c][k + tig];
                bf[fn][1] = Bs[c][k + tig + 4];
            }
#pragma unroll
            for (int fm = 0; fm < 4; fm++)
#pragma unroll
                for (int fn = 0; fn < 4; fn++)
                    mma_tf32(acc[fm][fn], af[fm][0], af[fm][1], af[fm][2], af[fm][3],
                             bf[fn][0], bf[fn][1]);
        }
        __syncthreads();
    }

#pragma unroll
    for (int fm = 0; fm < 4; fm++) {
        int r = m0 + wr * 64 + fm * 16 + l4;
#pragma unroll
        for (int fn = 0; fn < 4; fn++) {
            int c = n0 + wc * 32 + fn * 8 + 2 * tig;
            float bias0 = b1[c] + b2[c];
            float bias1 = b1[c + 1] + b2[c + 1];
            g_G[(size_t)r * Ndim + c]           = acc[fm][fn][0] + bias0;
            g_G[(size_t)r * Ndim + c + 1]       = acc[fm][fn][1] + bias1;
            g_G[(size_t)(r + 8) * Ndim + c]     = acc[fm][fn][2] + bias0;
            g_G[(size_t)(r + 8) * Ndim + c + 1] = acc[fm][fn][3] + bias1;
        }
    }
}

// ---------------- persistent recurrent LSTM pass -------------------------------
// h in PERMUTED fragment layout; staged to SMEM via 4-stage cp.async.
// PRODUCER-GROUP PIPELINED SYNC: mma stage s consumes k in [s*H/4,(s+1)*H/4),
// produced by CTAs [16s,16s+16). Each stage waits only its 16 producer flags,
// interleaved 2 stages ahead of consumption — slowest CTA gates only the last
// stage. A CTA reaches its epilogue only after all 4 waits (= all 64 flags >= t),
// which preserves the old full-barrier WAR guarantee on the h ping-pong.
template <int H>
__global__ void __launch_bounds__(256, 1) lstm_rec(const float* __restrict__ Whh,
                                                   int h0FromEnc, int outSel,
                                                   float* __restrict__ outFinal,
                                                   int saveFinal) {
    constexpr int HW = H / 64;
    constexpr int GW = 4 * HW;
    constexpr int NF = (GW / 16 > 0) ? GW / 16 : 1;
    constexpr int GWP = GW + 1;
    constexpr int Kd8 = H / 8;
    constexpr int NST = 4;                   // pipeline stages (= flag groups of 16 CTAs)
    constexpr int KsPS = Kd8 / NST;          // k-steps per stage
    constexpr int EPT = (64 * HW) / 256;     // cell elems per thread
    constexpr int NCHK = 4 * KsPS * 32;      // 16B chunks per stage

    extern __shared__ unsigned char smraw[];
    uint32_t* WhsP = (uint32_t*)smraw;               // GW*H u32 (permuted weights)
    uint32_t* hsmP = WhsP + GW * H;                  // 64*H u32 (permuted h)
    float* gsm = (float*)(hsmP + 64 * H);            // 64*GWP
    float* csm = gsm + 64 * GWP;                     // 64*HW

    const int tid = threadIdx.x, bid = blockIdx.x;
    const int wid = tid >> 5, lane = tid & 31, l4 = lane >> 2, tig = lane & 3;
    const int wm = wid & 3, wn = wid >> 2;
    const int j0 = bid * HW;
    const int cbase = wn * (GW / 2);

    float* __restrict__ Hout = (outSel == 0) ? g_seqA : (outSel == 1) ? g_seqB : outFinal;

    // ---- init: permuted Whh slice in SMEM (tf32) ----
    for (int d = tid; d < GW * H; d += 256) {
        int ci = d / (Kd8 * 64);
        int rem = d - ci * (Kd8 * 64);
        int ks = rem >> 6;
        int ln = (rem >> 1) & 31;
        int p = rem & 1;
        int dl4 = ln >> 2, dtig = ln & 3;
        int cc = ci * 8 + dl4;
        int gate = cc / HW, u = cc % HW;
        int k = ks * 8 + dtig + p * 4;
        WhsP[d] = f2tf32(Whh[((size_t)(gate * H + j0 + u)) * H + k]);
    }
    // ---- init: h0 (permuted) and c0 ----
    for (int e = tid; e < 64 * HW; e += 256) {
        int b = e / HW, u = e - b * HW;
        int ug = j0 + u;
        int P = ((((b >> 4) * Kd8 + (ug >> 3)) * 32 + (b & 7) * 4 + (ug & 3)) << 2)
                + ((b >> 3) & 1) + (((ug >> 2) & 1) << 1);
        if (h0FromEnc) {
            csm[e] = g_cT[b * H + ug];
            g_hbuf[0][P] = g_hTp[P];
        } else {
            csm[e] = 0.0f;
            g_hbuf[0][P] = 0.0f;
        }
    }
    if (tid == 0) g_fl[bid] = 0;    // reset flags for this launch / replay
    atomic_bar();                    // replay-safe; makes resets + init visible

    const uint32_t hsm_base = smem_u32(hsmP);

    for (int t = 0; t < TT; t++) {
        const float* __restrict__ hsrc = g_hbuf[t & 1];

        // prefetch G[t] into registers FIRST (DRAM latency hides under cp.async + mma)
        float Gi[EPT], Gf[EPT], Gg[EPT], Go[EPT];
        {
            const float* Gt = g_G + ((size_t)t * BB) * (4 * H);
#pragma unroll
            for (int ei = 0; ei < EPT; ei++) {
                int e = tid + ei * 256;
                int b = e / HW, u = e - b * HW;
                const float* gp = Gt + (size_t)b * (4 * H) + j0 + u;
                Gi[ei] = gp[0]; Gf[ei] = gp[H]; Gg[ei] = gp[2 * H]; Go[ei] = gp[3 * H];
            }
        }

        auto issue_cpa = [&](int s) {
            for (int c = tid; c < NCHK; c += 256) {
                int mg = c / (KsPS * 32);
                int rem = c - mg * (KsPS * 32);
                int ksl = rem >> 5;
                int ln = rem & 31;
                int oi = ((mg * Kd8 + s * KsPS + ksl) * 32 + ln) << 2;  // u32 idx
                cpa16(hsm_base + oi * 4, hsrc + oi);
            }
            cp_commit();
        };

        // 2 accumulator banks per fn — breaks the HMMA RAW chain
        float acc[NF][2][4];
#pragma unroll
        for (int fn = 0; fn < NF; fn++)
#pragma unroll
            for (int bk = 0; bk < 2; bk++)
#pragma unroll
                for (int i = 0; i < 4; i++) acc[fn][bk][i] = 0.0f;

        // prologue: stages 0 and 1 (wait producers, then load)
        wait_group_flags(0, t);
        issue_cpa(0);
        wait_group_flags(1, t);
        issue_cpa(1);

        // ---- staged mma, 2 stages ahead on loads ----
#pragma unroll
        for (int s = 0; s < NST; s++) {
            if (s + 2 < NST) {
                wait_group_flags(s + 2, t);
                issue_cpa(s + 2);
            }
            if (s == 0)      cp_waitg<2>();
            else if (s == 1) cp_waitg<2>();
            else if (s == 2) cp_waitg<1>();
            else             cp_waitg<0>();
            __syncthreads();
#pragma unroll 4
            for (int ks = s * KsPS; ks < (s + 1) * KsPS; ks++) {
                uint4 av = *(const uint4*)&hsmP[(((wm * Kd8 + ks) * 32 + lane) << 2)];
                const int bk = ks & 1;
#pragma unroll
                for (int fn = 0; fn < NF; fn++) {
                    int ci = (cbase >> 3) + fn;
                    uint2 bv = *(const uint2*)&WhsP[(ci * Kd8 + ks) * 64 + lane * 2];
                    mma_tf32(acc[fn][bk], av.x, av.y, av.z, av.w, bv.x, bv.y);
                }
            }
        }

        // gate accumulators (banks merged) -> SMEM (warp-exclusive regions)
        {
            int r = wm * 16 + l4;
#pragma unroll
            for (int fn = 0; fn < NF; fn++) {
                int cc = cbase + fn * 8 + 2 * tig;
                gsm[r * GWP + cc]           = acc[fn][0][0] + acc[fn][1][0];
                gsm[r * GWP + cc + 1]       = acc[fn][0][1] + acc[fn][1][1];
                gsm[(r + 8) * GWP + cc]     = acc[fn][0][2] + acc[fn][1][2];
                gsm[(r + 8) * GWP + cc + 1] = acc[fn][0][3] + acc[fn][1][3];
            }
        }
        __syncthreads();

        // fused LSTM cell; store h permuted + tf32-rounded
        const int nxt = (t & 1) ^ 1;
#pragma unroll
        for (int ei = 0; ei < EPT; ei++) {
            int e = tid + ei * 256;
            int b = e / HW, u = e - b * HW;
            float xi = gsm[b * GWP + u]          + Gi[ei];
            float xf = gsm[b * GWP + HW + u]     + Gf[ei];
            float xg = gsm[b * GWP + 2 * HW + u] + Gg[ei];
            float xo = gsm[b * GWP + 3 * HW + u] + Go[ei];
            float cv = sigf(xf) * csm[e] + sigf(xi) * tanhf(xg);
            float hv = sigf(xo) * tanhf(cv);
            csm[e] = cv;
            int ug = j0 + u;
            int P = ((((b >> 4) * Kd8 + (ug >> 3)) * 32 + (b & 7) * 4 + (ug & 3)) << 2)
                    + ((b >> 3) & 1) + (((ug >> 2) & 1) << 1);
            float hr = __uint_as_float(f2tf32(hv));
            g_hbuf[nxt][P] = hr;
            if (outSel == 2)
                Hout[((size_t)b * TT + t) * H + ug] = hv;    // (B,T,H) final out
            else
                Hout[((size_t)t * BB + b) * H + ug] = hv;    // (T,B,H) sequence
            if (saveFinal && t == TT - 1) {
                g_hTp[P] = hr;
                g_cT[b * H + ug] = cv;
            }
        }
        // post our flag: h(t) output fully stored
        __syncthreads();
        if (tid == 0)
            asm volatile("st.release.gpu.b32 [%0], %1;"
                         :: "l"(&g_fl[bid]), "r"(t + 1) : "memory");
    }
}

// ---------------- host ----------------
static const int SM512 = (32 * 512 + 64 * 512 + 64 * 33 + 64 * 8) * 4;   // 207,104 B
static const int SM256 = (16 * 256 + 64 * 256 + 64 * 17 + 64 * 4) * 4;   //  87,296 B

extern "C" void kernel_launch(void* const* d_in, const int* in_sizes, int n_in,
                              void* d_out, int out_size) {
    (void)in_sizes; (void)n_in; (void)out_size;
    const float* x = (const float*)d_in[0];
    const float* p[21];
    for (int i = 0; i < 21; i++) p[i] = (const float*)d_in[i];

    cudaFuncSetAttribute(lstm_rec<512>, cudaFuncAttributeMaxDynamicSharedMemorySize, SM512);
    cudaFuncSetAttribute(lstm_rec<256>, cudaFuncAttributeMaxDynamicSharedMemorySize, SM256);

    dim3 g2048(16, 256), g1024(8, 256);

    // encoder L0: x -> seqA
    gemm_input<<<g2048, 256>>>(0, x, p[1], p[3], p[4], 256, 2048, 0);
    lstm_rec<512><<<64, 256, SM512>>>(p[2], 0, 0, nullptr, 0);
    // encoder L1: seqA -> seqB, save (hT, cT)
    gemm_input<<<g2048, 256>>>(1, x, p[5], p[7], p[8], 512, 2048, 0);
    lstm_rec<512><<<64, 256, SM512>>>(p[6], 0, 1, nullptr, 1);
    // decoder L0: reversed x -> seqA, init from (hT, cT)
    gemm_input<<<g2048, 256>>>(0, x, p[9], p[11], p[12], 256, 2048, 1);
    lstm_rec<512><<<64, 256, SM512>>>(p[10], 1, 0, nullptr, 0);
    // decoder L1: seqA -> seqB
    gemm_input<<<g2048, 256>>>(1, x, p[13], p[15], p[16], 512, 2048, 0);
    lstm_rec<512><<<64, 256, SM512>>>(p[14], 0, 1, nullptr, 0);
    // decoder L2: seqB -> d_out (B,T,256)
    gemm_input<<<g1024, 256>>>(2, x, p[17], p[19], p[20], 512, 1024, 0);
    lstm_rec<256><<<64, 256, SM256>>>(p[18], 0, 2, (float*)d_out, 0);
}

// round 13
// speedup vs baseline: 1.1117x; 1.1117x over previous
#include <cuda_runtime.h>
#include <cstdint>
#include <cstddef>

#define TT 512
#define BB 64
#define NCTA 64

// ---------------- static scratch ----------------
__device__ float g_seqA[(size_t)TT * BB * 512];   // layer-output sequence (T,B,H)
__device__ float g_seqB[(size_t)TT * BB * 512];
__device__ float g_G[(size_t)TT * BB * 2048];     // precomputed input gates (T*B, 4H)
__device__ float g_hbuf[2][BB * 512];             // recurrent h: stage-major permuted tf32
__device__ float g_hTp[BB * 512];                 // encoder final h (permuted tf32)
__device__ float g_cT[BB * 512];                  // encoder final c (full precision)
__device__ int g_fl[NCTA];                        // per-CTA monotonic step flags
__device__ int g_barCount;
__device__ volatile int g_barGen;

// ---------------- helpers ----------------
__device__ __forceinline__ uint32_t f2tf32(float f) {
    uint32_t u;
    asm("cvt.rna.tf32.f32 %0, %1;" : "=r"(u) : "f"(f));
    return u;
}

__device__ __forceinline__ void mma_tf32(float c[4], uint32_t a0, uint32_t a1,
                                         uint32_t a2, uint32_t a3,
                                         uint32_t b0, uint32_t b1) {
    asm volatile(
        "mma.sync.aligned.m16n8k8.row.col.f32.tf32.tf32.f32 "
        "{%0,%1,%2,%3}, {%4,%5,%6,%7}, {%8,%9}, {%0,%1,%2,%3};"
        : "+f"(c[0]), "+f"(c[1]), "+f"(c[2]), "+f"(c[3])
        : "r"(a0), "r"(a1), "r"(a2), "r"(a3), "r"(b0), "r"(b1));
}

__device__ __forceinline__ float sigf(float x) { return 1.0f / (1.0f + __expf(-x)); }

__device__ __forceinline__ uint32_t smem_u32(const void* p) {
    uint32_t a;
    asm("{ .reg .u64 t; cvta.to.shared.u64 t, %1; cvt.u32.u64 %0, t; }" : "=r"(a) : "l"(p));
    return a;
}

// mbarrier primitives (bulk-copy completion tracking)
__device__ __forceinline__ void mbar_init(uint32_t bar, uint32_t count) {
    asm volatile("mbarrier.init.shared.b64 [%0], %1;" :: "r"(bar), "r"(count) : "memory");
}
__device__ __forceinline__ void mbar_expect_tx(uint32_t bar, uint32_t bytes) {
    asm volatile("mbarrier.arrive.expect_tx.shared.b64 _, [%0], %1;"
                 :: "r"(bar), "r"(bytes) : "memory");
}
__device__ __forceinline__ void bulk_g2s(uint32_t dst, const void* src,
                                         uint32_t bytes, uint32_t bar) {
    asm volatile(
        "cp.async.bulk.shared::cta.global.mbarrier::complete_tx::bytes [%0], [%1], %2, [%3];"
        :: "r"(dst), "l"(src), "r"(bytes), "r"(bar) : "memory");
}
__device__ __forceinline__ void mbar_wait(uint32_t bar, uint32_t parity) {
    uint32_t done;
    asm volatile(
        "{\n\t.reg .pred p;\n\t"
        "mbarrier.try_wait.parity.acquire.cta.shared::cta.b64 p, [%1], %2;\n\t"
        "selp.b32 %0, 1, 0, p;\n\t}"
        : "=r"(done) : "r"(bar), "r"(parity) : "memory");
    while (!done) {
        asm volatile(
            "{\n\t.reg .pred p;\n\t"
            "mbarrier.try_wait.parity.acquire.cta.shared::cta.b64 p, [%1], %2, 0x989680;\n\t"
            "selp.b32 %0, 1, 0, p;\n\t}"
            : "=r"(done) : "r"(bar), "r"(parity) : "memory");
    }
}

// legacy atomic barrier (replay-safe) — used ONCE per launch after init/reset
__device__ __forceinline__ void atomic_bar() {
    __threadfence();
    __syncthreads();
    if (threadIdx.x == 0) {
        int g = g_barGen;
        if (atomicAdd(&g_barCount, 1) == NCTA - 1) {
            g_barCount = 0;
            __threadfence();
            g_barGen = g + 1;
        } else {
            while (g_barGen == g) { __nanosleep(64); }
        }
        __threadfence();
    }
    __syncthreads();
}

// full-grid flag barrier (R10-proven): one wait per step, sleep-every-poll.
__device__ __forceinline__ void fbar(int idx) {
    __syncthreads();
    if (threadIdx.x == 0)
        asm volatile("st.release.gpu.b32 [%0], %1;" :: "l"(&g_fl[blockIdx.x]), "r"(idx) : "memory");
    if (threadIdx.x < NCTA) {
        int v;
        asm volatile("ld.acquire.gpu.b32 %0, [%1];" : "=r"(v) : "l"(&g_fl[threadIdx.x]) : "memory");
        while (v < idx) {
            __nanosleep(24);
            asm volatile("ld.acquire.gpu.b32 %0, [%1];" : "=r"(v) : "l"(&g_fl[threadIdx.x]) : "memory");
        }
    }
    __syncthreads();
}

// ---------------- input GEMM: G = src @ W^T + b1 + b2 --------------------------
__global__ void __launch_bounds__(256) gemm_input(int srcSel,
                                                  const float* __restrict__ xin,
                                                  const float* __restrict__ W,
                                                  const float* __restrict__ b1,
                                                  const float* __restrict__ b2,
                                                  int Kdim, int Ndim, int rev) {
    __shared__ __align__(16) uint32_t As[128][36];
    __shared__ __align__(16) uint32_t Bs[128][36];

    const float* __restrict__ S = (srcSel == 0) ? xin : (srcSel == 1) ? g_seqA : g_seqB;

    int tid = threadIdx.x;
    int wid = tid >> 5, lane = tid & 31, l4 = lane >> 2, tig = lane & 3;
    int wr = wid >> 2, wc = wid & 3;
    int m0 = blockIdx.y * 128, n0 = blockIdx.x * 128;

    size_t aoff[4];
    const float* wrow[4];
#pragma unroll
    for (int i = 0; i < 4; i++) {
        int v = tid + i * 256;
        int row = v >> 3, kv = v & 7;
        int m = m0 + row;
        size_t off;
        if (srcSel == 0) {
            int t = m >> 6;
            if (rev) t = TT - 1 - t;
            off = ((size_t)(m & 63) * TT + t) * Kdim;
        } else {
            off = (size_t)m * Kdim;
        }
        aoff[i] = off + kv * 4;
        wrow[i] = W + (size_t)(n0 + row) * Kdim + kv * 4;
    }

    float acc[4][4][4];
#pragma unroll
    for (int fm = 0; fm < 4; fm++)
#pragma unroll
        for (int fn = 0; fn < 4; fn++)
#pragma unroll
            for (int i = 0; i < 4; i++) acc[fm][fn][i] = 0.0f;

    float4 ra[4], rb[4];
#pragma unroll
    for (int i = 0; i < 4; i++) {
        ra[i] = *(const float4*)(S + aoff[i]);
        rb[i] = *(const float4*)(wrow[i]);
    }

    for (int kt = 0; kt < Kdim; kt += 32) {
#pragma unroll
        for (int i = 0; i < 4; i++) {
            int v = tid + i * 256;
            int row = v >> 3, kv = v & 7;
            uint4 ua, ub;
            ua.x = f2tf32(ra[i].x); ua.y = f2tf32(ra[i].y);
            ua.z = f2tf32(ra[i].z); ua.w = f2tf32(ra[i].w);
            ub.x = f2tf32(rb[i].x); ub.y = f2tf32(rb[i].y);
            ub.z = f2tf32(rb[i].z); ub.w = f2tf32(rb[i].w);
            *(uint4*)&As[row][kv * 4] = ua;
            *(uint4*)&Bs[row][kv * 4] = ub;
        }
        __syncthreads();

        if (kt + 32 < Kdim) {
#pragma unroll
            for (int i = 0; i < 4; i++) {
                ra[i] = *(const float4*)(S + aoff[i] + kt + 32);
                rb[i] = *(const float4*)(wrow[i] + kt + 32);
            }
        }

#pragma unroll
        for (int ks = 0; ks < 4; ks++) {
            const int k = ks * 8;
            uint32_t af[4][4], bf[4][2];
#pragma unroll
            for (int fm = 0; fm < 4; fm++) {
                int r = wr * 64 + fm * 16 + l4;
                af[fm][0] = As[r][k + tig];
                af[fm][1] = As[r + 8][k + tig];
                af[fm][2] = As[r][k + tig + 4];
                af[fm][3] = As[r + 8][k + tig + 4];
            }
#pragma unroll
            for (int fn = 0; fn < 4; fn++) {
                int c = wc * 32 + fn * 8 + l4;
                bf[fn][0] = Bs[c][k + tig];
                bf[fn][1] = Bs[c][k + tig + 4];
            }
#pragma unroll
            for (int fm = 0; fm < 4; fm++)
#pragma unroll
                for (int fn = 0; fn < 4; fn++)
                    mma_tf32(acc[fm][fn], af[fm][0], af[fm][1], af[fm][2], af[fm][3],
                             bf[fn][0], bf[fn][1]);
        }
        __syncthreads();
    }

#pragma unroll
    for (int fm = 0; fm < 4; fm++) {
        int r = m0 + wr * 64 + fm * 16 + l4;
#pragma unroll
        for (int fn = 0; fn < 4; fn++) {
            int c = n0 + wc * 32 + fn * 8 + 2 * tig;
            float bias0 = b1[c] + b2[c];
            float bias1 = b1[c + 1] + b2[c + 1];
            g_G[(size_t)r * Ndim + c]           = acc[fm][fn][0] + bias0;
            g_G[(size_t)r * Ndim + c + 1]       = acc[fm][fn][1] + bias1;
            g_G[(size_t)(r + 8) * Ndim + c]     = acc[fm][fn][2] + bias0;
            g_G[(size_t)(r + 8) * Ndim + c + 1] = acc[fm][fn][3] + bias1;
        }
    }
}

// ---------------- persistent recurrent LSTM pass -------------------------------
// h in STAGE-MAJOR permuted fragment layout: block index blk = (s*4+mg)*KsPS+ksl
// (s = k-stage, mg = b>>4, ksl = local k-step); element
//   P(b,k) = (blk*32 + (b&7)*4 + (k&3))*4 + ((b>>3)&1) + ((k>>2)&1)*2
// Stage s occupies a CONTIGUOUS 32KB region -> one cp.async.bulk per stage per
// step (4 TMA issues replace 8192 cp.async.cg LDGSTS ops that contended with
// the LDS fragment feed on the MIO pipe). Completion via mbarrier complete_tx,
// parity = t&1 (one flip per step). Single end-of-step fbar (R10-proven).
template <int H>
__global__ void __launch_bounds__(256, 1) lstm_rec(const float* __restrict__ Whh,
                                                   int h0FromEnc, int outSel,
                                                   float* __restrict__ outFinal,
                                                   int saveFinal) {
    constexpr int HW = H / 64;
    constexpr int GW = 4 * HW;
    constexpr int NF = (GW / 16 > 0) ? GW / 16 : 1;
    constexpr int GWP = GW + 1;
    constexpr int Kd8 = H / 8;
    constexpr int NST = 4;                     // k-stages
    constexpr int KsPS = Kd8 / NST;            // k-steps per stage
    constexpr int EPT = (64 * HW) / 256;       // cell elems per thread
    constexpr uint32_t STG_BYTES = 4 * KsPS * 32 * 16;   // bytes per stage (contig)
    constexpr int STG_FLOATS = (int)STG_BYTES / 4;

    extern __shared__ unsigned char smraw[];
    uint64_t* mbar = (uint64_t*)smraw;                   // 4 mbarriers (64B reserved)
    uint32_t* WhsP = (uint32_t*)(smraw + 64);            // GW*H u32 (permuted weights)
    uint32_t* hsmP = WhsP + GW * H;                      // 64*H u32 (stage-major h)
    float* gsm = (float*)(hsmP + 64 * H);                // 64*GWP
    float* csm = gsm + 64 * GWP;                         // 64*HW

    const int tid = threadIdx.x, bid = blockIdx.x;
    const int wid = tid >> 5, lane = tid & 31, l4 = lane >> 2, tig = lane & 3;
    const int wm = wid & 3, wn = wid >> 2;
    const int j0 = bid * HW;
    const int cbase = wn * (GW / 2);

    float* __restrict__ Hout = (outSel == 0) ? g_seqA : (outSel == 1) ? g_seqB : outFinal;

    // ---- init: permuted Whh slice in SMEM (tf32; layout unchanged) ----
    for (int d = tid; d < GW * H; d += 256) {
        int ci = d / (Kd8 * 64);
        int rem = d - ci * (Kd8 * 64);
        int ks = rem >> 6;
        int ln = (rem >> 1) & 31;
        int p = rem & 1;
        int dl4 = ln >> 2, dtig = ln & 3;
        int cc = ci * 8 + dl4;
        int gate = cc / HW, u = cc % HW;
        int k = ks * 8 + dtig + p * 4;
        WhsP[d] = f2tf32(Whh[((size_t)(gate * H + j0 + u)) * H + k]);
    }
    // ---- init: h0 (stage-major permuted) and c0 ----
    for (int e = tid; e < 64 * HW; e += 256) {
        int b = e / HW, u = e - b * HW;
        int ug = j0 + u;
        int ksb = ug >> 3;
        int blk = ((ksb / KsPS) * 4 + (b >> 4)) * KsPS + (ksb % KsPS);
        int P = ((blk * 32 + (b & 7) * 4 + (ug & 3)) << 2)
                + ((b >> 3) & 1) + (((ug >> 2) & 1) << 1);
        if (h0FromEnc) {
            csm[e] = g_cT[b * H + ug];
            g_hbuf[0][P] = g_hTp[P];
        } else {
            csm[e] = 0.0f;
            g_hbuf[0][P] = 0.0f;
        }
    }
    const uint32_t mbar_base = smem_u32(mbar);
    const uint32_t hsm_base = smem_u32(hsmP);
    if (tid == 0) {
        g_fl[bid] = 0;                          // reset flags for launch / replay
#pragma unroll
        for (int s = 0; s < NST; s++) mbar_init(mbar_base + s * 8, 1);
    }
    atomic_bar();                                // replay-safe; resets + init visible

    for (int t = 0; t < TT; t++) {
        const float* __restrict__ hsrc = g_hbuf[t & 1];

        // prefetch G[t] into registers FIRST (DRAM latency hides under bulk + mma)
        float Gi[EPT], Gf[EPT], Gg[EPT], Go[EPT];
        {
            const float* Gt = g_G + ((size_t)t * BB) * (4 * H);
#pragma unroll
            for (int ei = 0; ei < EPT; ei++) {
                int e = tid + ei * 256;
                int b = e / HW, u = e - b * HW;
                const float* gp = Gt + (size_t)b * (4 * H) + j0 + u;
                Gi[ei] = gp[0]; Gf[ei] = gp[H]; Gg[ei] = gp[2 * H]; Go[ei] = gp[3 * H];
            }
        }

        // issue all 4 stage bulk copies (tid 0 only — 4 issue slots total)
        if (tid == 0) {
#pragma unroll
            for (int s = 0; s < NST; s++) {
                uint32_t bar = mbar_base + s * 8;
                mbar_expect_tx(bar, STG_BYTES);
                bulk_g2s(hsm_base + s * STG_BYTES, hsrc + (size_t)s * STG_FLOATS,
                         STG_BYTES, bar);
            }
        }

        // 2 accumulator banks per fn — breaks the HMMA RAW chain
        float acc[NF][2][4];
#pragma unroll
        for (int fn = 0; fn < NF; fn++)
#pragma unroll
            for (int bk = 0; bk < 2; bk++)
#pragma unroll
                for (int i = 0; i < 4; i++) acc[fn][bk][i] = 0.0f;

        // ---- staged mma; wait each stage's bulk completion (parity = t&1) ----
        const uint32_t par = (uint32_t)(t & 1);
#pragma unroll
        for (int s = 0; s < NST; s++) {
            mbar_wait(mbar_base + s * 8, par);
#pragma unroll 4
            for (int ksl = 0; ksl < KsPS; ksl++) {
                const int ks = s * KsPS + ksl;
                uint4 av = *(const uint4*)&hsmP[((((s * 4 + wm) * KsPS + ksl) * 32 + lane) << 2)];
                const int bk = ks & 1;
#pragma unroll
                for (int fn = 0; fn < NF; fn++) {
                    int ci = (cbase >> 3) + fn;
                    uint2 bv = *(const uint2*)&WhsP[(ci * Kd8 + ks) * 64 + lane * 2];
                    mma_tf32(acc[fn][bk], av.x, av.y, av.z, av.w, bv.x, bv.y);
                }
            }
        }

        // gate accumulators (banks merged) -> SMEM (warp-exclusive regions)
        {
            int r = wm * 16 + l4;
#pragma unroll
            for (int fn = 0; fn < NF; fn++) {
                int cc = cbase + fn * 8 + 2 * tig;
                gsm[r * GWP + cc]           = acc[fn][0][0] + acc[fn][1][0];
                gsm[r * GWP + cc + 1]       = acc[fn][0][1] + acc[fn][1][1];
                gsm[(r + 8) * GWP + cc]     = acc[fn][0][2] + acc[fn][1][2];
                gsm[(r + 8) * GWP + cc + 1] = acc[fn][0][3] + acc[fn][1][3];
            }
        }
        __syncthreads();

        // fused LSTM cell; store h stage-major permuted + tf32-rounded
        const int nxt = (t & 1) ^ 1;
#pragma unroll
        for (int ei = 0; ei < EPT; ei++) {
            int e = tid + ei * 256;
            int b = e / HW, u = e - b * HW;
            float xi = gsm[b * GWP + u]          + Gi[ei];
            float xf = gsm[b * GWP + HW + u]     + Gf[ei];
            float xg = gsm[b * GWP + 2 * HW + u] + Gg[ei];
            float xo = gsm[b * GWP + 3 * HW + u] + Go[ei];
            float cv = sigf(xf) * csm[e] + sigf(xi) * tanhf(xg);
            float hv = sigf(xo) * tanhf(cv);
            csm[e] = cv;
            int ug = j0 + u;
            int ksb = ug >> 3;
            int blk = ((ksb / KsPS) * 4 + (b >> 4)) * KsPS + (ksb % KsPS);
            int P = ((blk * 32 + (b & 7) * 4 + (ug & 3)) << 2)
                    + ((b >> 3) & 1) + (((ug >> 2) & 1) << 1);
            float hr = __uint_as_float(f2tf32(hv));
            g_hbuf[nxt][P] = hr;
            if (outSel == 2)
                Hout[((size_t)b * TT + t) * H + ug] = hv;    // (B,T,H) final out
            else
                Hout[((size_t)t * BB + b) * H + ug] = hv;    // (T,B,H) sequence
            if (saveFinal && t == TT - 1) {
                g_hTp[P] = hr;
                g_cT[b * H + ug] = cv;
            }
        }
        fbar(t + 1);
    }
}

// ---------------- host ----------------
static const int SM512 = 64 + (32 * 512 + 64 * 512 + 64 * 33 + 64 * 8) * 4;   // 207,168 B
static const int SM256 = 64 + (16 * 256 + 64 * 256 + 64 * 17 + 64 * 4) * 4;   //  87,360 B

extern "C" void kernel_launch(void* const* d_in, const int* in_sizes, int n_in,
                              void* d_out, int out_size) {
    (void)in_sizes; (void)n_in; (void)out_size;
    const float* x = (const float*)d_in[0];
    const float* p[21];
    for (int i = 0; i < 21; i++) p[i] = (const float*)d_in[i];

    cudaFuncSetAttribute(lstm_rec<512>, cudaFuncAttributeMaxDynamicSharedMemorySize, SM512);
    cudaFuncSetAttribute(lstm_rec<256>, cudaFuncAttributeMaxDynamicSharedMemorySize, SM256);

    dim3 g2048(16, 256), g1024(8, 256);

    // encoder L0: x -> seqA
    gemm_input<<<g2048, 256>>>(0, x, p[1], p[3], p[4], 256, 2048, 0);
    lstm_rec<512><<<64, 256, SM512>>>(p[2], 0, 0, nullptr, 0);
    // encoder L1: seqA -> seqB, save (hT, cT)
    gemm_input<<<g2048, 256>>>(1, x, p[5], p[7], p[8], 512, 2048, 0);
    lstm_rec<512><<<64, 256, SM512>>>(p[6], 0, 1, nullptr, 1);
    // decoder L0: reversed x -> seqA, init from (hT, cT)
    gemm_input<<<g2048, 256>>>(0, x, p[9], p[11], p[12], 256, 2048, 1);
    lstm_rec<512><<<64, 256, SM512>>>(p[10], 1, 0, nullptr, 0);
    // decoder L1: seqA -> seqB
    gemm_input<<<g2048, 256>>>(1, x, p[13], p[15], p[16], 512, 2048, 0);
    lstm_rec<512><<<64, 256, SM512>>>(p[14], 0, 1, nullptr, 0);
    // decoder L2: seqB -> d_out (B,T,256)
    gemm_input<<<g1024, 256>>>(2, x, p[17], p[19], p[20], 512, 1024, 0);
    lstm_rec<256><<<64, 256, SM256>>>(p[18], 0, 2, (float*)d_out, 0);
}

// round 15
// speedup vs baseline: 1.1321x; 1.0183x over previous
#include <cuda_runtime.h>
#include <cstdint>
#include <cstddef>

#define TT 512
#define BB 64
#define NCTA 64

// ---------------- static scratch ----------------
__device__ float g_seqA[(size_t)TT * BB * 512];   // layer-output sequence (T,B,H)
__device__ float g_seqB[(size_t)TT * BB * 512];
__device__ float g_G[(size_t)TT * BB * 2048];     // precomputed input gates (T*B, 4H)
__device__ float g_hbuf[2][BB * 512];             // recurrent h: stage-major permuted tf32
__device__ float g_hTp[BB * 512];                 // encoder final h (permuted tf32)
__device__ float g_cT[BB * 512];                  // encoder final c (full precision)
__device__ int g_fl[NCTA];                        // per-CTA monotonic step flags
__device__ int g_barCount;
__device__ volatile int g_barGen;

// ---------------- helpers ----------------
__device__ __forceinline__ uint32_t f2tf32(float f) {
    uint32_t u;
    asm("cvt.rna.tf32.f32 %0, %1;" : "=r"(u) : "f"(f));
    return u;
}

__device__ __forceinline__ void mma_tf32(float c[4], uint32_t a0, uint32_t a1,
                                         uint32_t a2, uint32_t a3,
                                         uint32_t b0, uint32_t b1) {
    asm volatile(
        "mma.sync.aligned.m16n8k8.row.col.f32.tf32.tf32.f32 "
        "{%0,%1,%2,%3}, {%4,%5,%6,%7}, {%8,%9}, {%0,%1,%2,%3};"
        : "+f"(c[0]), "+f"(c[1]), "+f"(c[2]), "+f"(c[3])
        : "r"(a0), "r"(a1), "r"(a2), "r"(a3), "r"(b0), "r"(b1));
}

__device__ __forceinline__ float sigf(float x) { return 1.0f / (1.0f + __expf(-x)); }

__device__ __forceinline__ uint32_t smem_u32(const void* p) {
    uint32_t a;
    asm("{ .reg .u64 t; cvta.to.shared.u64 t, %1; cvt.u32.u64 %0, t; }" : "=r"(a) : "l"(p));
    return a;
}

// mbarrier primitives (bulk-copy completion tracking)
__device__ __forceinline__ void mbar_init(uint32_t bar, uint32_t count) {
    asm volatile("mbarrier.init.shared.b64 [%0], %1;" :: "r"(bar), "r"(count) : "memory");
}
__device__ __forceinline__ void mbar_expect_tx(uint32_t bar, uint32_t bytes) {
    asm volatile("mbarrier.arrive.expect_tx.shared.b64 _, [%0], %1;"
                 :: "r"(bar), "r"(bytes) : "memory");
}
__device__ __forceinline__ void bulk_g2s(uint32_t dst, const void* src,
                                         uint32_t bytes, uint32_t bar) {
    asm volatile(
        "cp.async.bulk.shared::cta.global.mbarrier::complete_tx::bytes [%0], [%1], %2, [%3];"
        :: "r"(dst), "l"(src), "r"(bytes), "r"(bar) : "memory");
}
__device__ __forceinline__ void mbar_wait(uint32_t bar, uint32_t parity) {
    uint32_t done;
    asm volatile(
        "{\n\t.reg .pred p;\n\t"
        "mbarrier.try_wait.parity.acquire.cta.shared::cta.b64 p, [%1], %2;\n\t"
        "selp.b32 %0, 1, 0, p;\n\t}"
        : "=r"(done) : "r"(bar), "r"(parity) : "memory");
    while (!done) {
        asm volatile(
            "{\n\t.reg .pred p;\n\t"
            "mbarrier.try_wait.parity.acquire.cta.shared::cta.b64 p, [%1], %2, 0x989680;\n\t"
            "selp.b32 %0, 1, 0, p;\n\t}"
            : "=r"(done) : "r"(bar), "r"(parity) : "memory");
    }
}

// legacy atomic barrier (replay-safe) — used ONCE per launch after init/reset
__device__ __forceinline__ void atomic_bar() {
    __threadfence();
    __syncthreads();
    if (threadIdx.x == 0) {
        int g = g_barGen;
        if (atomicAdd(&g_barCount, 1) == NCTA - 1) {
            g_barCount = 0;
            __threadfence();
            g_barGen = g + 1;
        } else {
            while (g_barGen == g) { __nanosleep(64); }
        }
        __threadfence();
    }
    __syncthreads();
}

// full-grid flag barrier: spin-first (fast wake), nanosleep only after long wait.
__device__ __forceinline__ void fbar(int idx) {
    __syncthreads();
    if (threadIdx.x == 0)
        asm volatile("st.release.gpu.b32 [%0], %1;" :: "l"(&g_fl[blockIdx.x]), "r"(idx) : "memory");
    if (threadIdx.x < NCTA) {
        int v, spins = 0;
        for (;;) {
            asm volatile("ld.acquire.gpu.b32 %0, [%1];" : "=r"(v) : "l"(&g_fl[threadIdx.x]) : "memory");
            if (v >= idx) break;
            if (++spins > 2048) __nanosleep(32);
        }
    }
    __syncthreads();
}

// ---------------- input GEMM: G = src @ W^T + b1 + b2 --------------------------
__global__ void __launch_bounds__(256) gemm_input(int srcSel,
                                                  const float* __restrict__ xin,
                                                  const float* __restrict__ W,
                                                  const float* __restrict__ b1,
                                                  const float* __restrict__ b2,
                                                  int Kdim, int Ndim, int rev) {
    __shared__ __align__(16) uint32_t As[128][36];
    __shared__ __align__(16) uint32_t Bs[128][36];

    const float* __restrict__ S = (srcSel == 0) ? xin : (srcSel == 1) ? g_seqA : g_seqB;

    int tid = threadIdx.x;
    int wid = tid >> 5, lane = tid & 31, l4 = lane >> 2, tig = lane & 3;
    int wr = wid >> 2, wc = wid & 3;
    int m0 = blockIdx.y * 128, n0 = blockIdx.x * 128;

    size_t aoff[4];
    const float* wrow[4];
#pragma unroll
    for (int i = 0; i < 4; i++) {
        int v = tid + i * 256;
        int row = v >> 3, kv = v & 7;
        int m = m0 + row;
        size_t off;
        if (srcSel == 0) {
            int t = m >> 6;
            if (rev) t = TT - 1 - t;
            off = ((size_t)(m & 63) * TT + t) * Kdim;
        } else {
            off = (size_t)m * Kdim;
        }
        aoff[i] = off + kv * 4;
        wrow[i] = W + (size_t)(n0 + row) * Kdim + kv * 4;
    }

    float acc[4][4][4];
#pragma unroll
    for (int fm = 0; fm < 4; fm++)
#pragma unroll
        for (int fn = 0; fn < 4; fn++)
#pragma unroll
            for (int i = 0; i < 4; i++) acc[fm][fn][i] = 0.0f;

    float4 ra[4], rb[4];
#pragma unroll
    for (int i = 0; i < 4; i++) {
        ra[i] = *(const float4*)(S + aoff[i]);
        rb[i] = *(const float4*)(wrow[i]);
    }

    for (int kt = 0; kt < Kdim; kt += 32) {
#pragma unroll
        for (int i = 0; i < 4; i++) {
            int v = tid + i * 256;
            int row = v >> 3, kv = v & 7;
            uint4 ua, ub;
            ua.x = f2tf32(ra[i].x); ua.y = f2tf32(ra[i].y);
            ua.z = f2tf32(ra[i].z); ua.w = f2tf32(ra[i].w);
            ub.x = f2tf32(rb[i].x); ub.y = f2tf32(rb[i].y);
            ub.z = f2tf32(rb[i].z); ub.w = f2tf32(rb[i].w);
            *(uint4*)&As[row][kv * 4] = ua;
            *(uint4*)&Bs[row][kv * 4] = ub;
        }
        __syncthreads();

        if (kt + 32 < Kdim) {
#pragma unroll
            for (int i = 0; i < 4; i++) {
                ra[i] = *(const float4*)(S + aoff[i] + kt + 32);
                rb[i] = *(const float4*)(wrow[i] + kt + 32);
            }
        }

#pragma unroll
        for (int ks = 0; ks < 4; ks++) {
            const int k = ks * 8;
            uint32_t af[4][4], bf[4][2];
#pragma unroll
            for (int fm = 0; fm < 4; fm++) {
                int r = wr * 64 + fm * 16 + l4;
                af[fm][0] = As[r][k + tig];
                af[fm][1] = As[r + 8][k + tig];
                af[fm][2] = As[r][k + tig + 4];
                af[fm][3] = As[r + 8][k + tig + 4];
            }
#pragma unroll
            for (int fn = 0; fn < 4; fn++) {
                int c = wc * 32 + fn * 8 + l4;
                bf[fn][0] = Bs[c][k + tig];
                bf[fn][1] = Bs[c][k + tig + 4];
            }
#pragma unroll
            for (int fm = 0; fm < 4; fm++)
#pragma unroll
                for (int fn = 0; fn < 4; fn++)
                    mma_tf32(acc[fm][fn], af[fm][0], af[fm][1], af[fm][2], af[fm][3],
                             bf[fn][0], bf[fn][1]);
        }
        __syncthreads();
    }

#pragma unroll
    for (int fm = 0; fm < 4; fm++) {
        int r = m0 + wr * 64 + fm * 16 + l4;
#pragma unroll
        for (int fn = 0; fn < 4; fn++) {
            int c = n0 + wc * 32 + fn * 8 + 2 * tig;
            float bias0 = b1[c] + b2[c];
            float bias1 = b1[c + 1] + b2[c + 1];
            g_G[(size_t)r * Ndim + c]           = acc[fm][fn][0] + bias0;
            g_G[(size_t)r * Ndim + c + 1]       = acc[fm][fn][1] + bias1;
            g_G[(size_t)(r + 8) * Ndim + c]     = acc[fm][fn][2] + bias0;
            g_G[(size_t)(r + 8) * Ndim + c + 1] = acc[fm][fn][3] + bias1;
        }
    }
}

// ---------------- persistent recurrent LSTM pass -------------------------------
// 512 threads / 16 warps: warp (wm, wn, wk) = (m-tile, n-half, K-HALF). K-split
// doubles warps per SMSP (2->4) to hide the LDS->mma RAW chain; partial gate
// sums land in gsm[wk] and are merged in the epilogue (fp32 reassociation only).
// Warp->SMSP packing wm=wid&3, wk=(wid>>2)&1 mixes K-halves on each SMSP so
// early-stage warps run while late-stage warps await TMA stages 2-3.
// h stage-major permuted; 4 cp.async.bulk per step, mbarrier parity = t&1.
template <int H>
__global__ void __launch_bounds__(512, 1) lstm_rec(const float* __restrict__ Whh,
                                                   int h0FromEnc, int outSel,
                                                   float* __restrict__ outFinal,
                                                   int saveFinal) {
    constexpr int THR = 512;
    constexpr int HW = H / 64;
    constexpr int GW = 4 * HW;
    constexpr int NF = (GW / 16 > 0) ? GW / 16 : 1;   // 8-wide frags per n-half
    constexpr int GWP = GW + 1;
    constexpr int Kd8 = H / 8;
    constexpr int NST = 4;                     // TMA k-stages
    constexpr int KsPS = Kd8 / NST;            // k-steps per stage
    constexpr uint32_t STG_BYTES = 4 * KsPS * 32 * 16;   // bytes per stage (contig)
    constexpr int STG_FLOATS = (int)STG_BYTES / 4;
    constexpr int NCELL = 64 * HW;             // cell elems per CTA

    extern __shared__ unsigned char smraw[];
    uint64_t* mbar = (uint64_t*)smraw;                   // 4 mbarriers (64B reserved)
    uint32_t* WhsP = (uint32_t*)(smraw + 64);            // GW*H u32 (permuted weights)
    uint32_t* hsmP = WhsP + GW * H;                      // 64*H u32 (stage-major h)
    float* gsm = (float*)(hsmP + 64 * H);                // 2 * 64 * GWP (k-half partials)
    float* csm = gsm + 2 * 64 * GWP;                     // 64*HW

    const int tid = threadIdx.x, bid = blockIdx.x;
    const int wid = tid >> 5, lane = tid & 31, l4 = lane >> 2, tig = lane & 3;
    const int wm = wid & 3;            // m-tile (also SMSP id)
    const int wk = (wid >> 2) & 1;     // K-half
    const int wn = wid >> 3;           // n-half
    const int j0 = bid * HW;
    const int cbase = wn * (GW / 2);

    float* __restrict__ Hout = (outSel == 0) ? g_seqA : (outSel == 1) ? g_seqB : outFinal;

    // ---- init: permuted Whh slice in SMEM (tf32; layout unchanged) ----
    for (int d = tid; d < GW * H; d += THR) {
        int ci = d / (Kd8 * 64);
        int rem = d - ci * (Kd8 * 64);
        int ks = rem >> 6;
        int ln = (rem >> 1) & 31;
        int p = rem & 1;
        int dl4 = ln >> 2, dtig = ln & 3;
        int cc = ci * 8 + dl4;
        int gate = cc / HW, u = cc % HW;
        int k = ks * 8 + dtig + p * 4;
        WhsP[d] = f2tf32(Whh[((size_t)(gate * H + j0 + u)) * H + k]);
    }
    // ---- init: h0 (stage-major permuted) and c0 ----
    for (int e = tid; e < NCELL; e += THR) {
        int b = e / HW, u = e - b * HW;
        int ug = j0 + u;
        int ksb = ug >> 3;
        int blk = ((ksb / KsPS) * 4 + (b >> 4)) * KsPS + (ksb % KsPS);
        int P = ((blk * 32 + (b & 7) * 4 + (ug & 3)) << 2)
                + ((b >> 3) & 1) + (((ug >> 2) & 1) << 1);
        if (h0FromEnc) {
            csm[e] = g_cT[b * H + ug];
            g_hbuf[0][P] = g_hTp[P];
        } else {
            csm[e] = 0.0f;
            g_hbuf[0][P] = 0.0f;
        }
    }
    const uint32_t mbar_base = smem_u32(mbar);
    const uint32_t hsm_base = smem_u32(hsmP);
    if (tid == 0) {
        g_fl[bid] = 0;                          // reset flags for launch / replay
#pragma unroll
        for (int s = 0; s < NST; s++) mbar_init(mbar_base + s * 8, 1);
    }
    atomic_bar();                                // replay-safe; resets + init visible

    for (int t = 0; t < TT; t++) {
        const float* __restrict__ hsrc = g_hbuf[t & 1];

        // prefetch G[t] (this thread's single cell element, if any)
        const int e = tid;
        const int b = e / HW, u = e - b * HW;
        float Gi = 0, Gf = 0, Gg = 0, Go = 0;
        if (e < NCELL) {
            const float* gp = g_G + ((size_t)t * BB + b) * (4 * H) + j0 + u;
            Gi = gp[0]; Gf = gp[H]; Gg = gp[2 * H]; Go = gp[3 * H];
        }

        // issue all 4 stage bulk copies (tid 0 only)
        if (tid == 0) {
#pragma unroll
            for (int s = 0; s < NST; s++) {
                uint32_t bar = mbar_base + s * 8;
                mbar_expect_tx(bar, STG_BYTES);
                bulk_g2s(hsm_base + s * STG_BYTES, hsrc + (size_t)s * STG_FLOATS,
                         STG_BYTES, bar);
            }
        }

        // 2 accumulator banks per fn — breaks the HMMA RAW chain
        float acc[NF][2][4];
#pragma unroll
        for (int fn = 0; fn < NF; fn++)
#pragma unroll
            for (int bk = 0; bk < 2; bk++)
#pragma unroll
                for (int i = 0; i < 4; i++) acc[fn][bk][i] = 0.0f;

        // ---- this warp's 2 stages (K-half wk) ----
        const uint32_t par = (uint32_t)(t & 1);
#pragma unroll
        for (int sl = 0; sl < 2; sl++) {
            const int s = wk * 2 + sl;
            mbar_wait(mbar_base + s * 8, par);
#pragma unroll 4
            for (int ksl = 0; ksl < KsPS; ksl++) {
                const int ks = s * KsPS + ksl;
                uint4 av = *(const uint4*)&hsmP[((((s * 4 + wm) * KsPS + ksl) * 32 + lane) << 2)];
                const int bk = ks & 1;
#pragma unroll
                for (int fn = 0; fn < NF; fn++) {
                    int ci = (cbase >> 3) + fn;
                    uint2 bv = *(const uint2*)&WhsP[(ci * Kd8 + ks) * 64 + lane * 2];
                    mma_tf32(acc[fn][bk], av.x, av.y, av.z, av.w, bv.x, bv.y);
                }
            }
        }

        // partial gate sums -> gsm[wk] (warp-exclusive regions per k-half buffer)
        {
            int r = wm * 16 + l4;
            float* gbuf = gsm + wk * (64 * GWP);
#pragma unroll
            for (int fn = 0; fn < NF; fn++) {
                int cc = cbase + fn * 8 + 2 * tig;
                gbuf[r * GWP + cc]           = acc[fn][0][0] + acc[fn][1][0];
                gbuf[r * GWP + cc + 1]       = acc[fn][0][1] + acc[fn][1][1];
                gbuf[(r + 8) * GWP + cc]     = acc[fn][0][2] + acc[fn][1][2];
                gbuf[(r + 8) * GWP + cc + 1] = acc[fn][0][3] + acc[fn][1][3];
            }
        }
        __syncthreads();

        // fused LSTM cell (merge K-half partials); store h stage-major + tf32
        const int nxt = (t & 1) ^ 1;
        if (e < NCELL) {
            const float* g0 = gsm;
            const float* g1 = gsm + 64 * GWP;
            float xi = g0[b * GWP + u]          + g1[b * GWP + u]          + Gi;
            float xf = g0[b * GWP + HW + u]     + g1[b * GWP + HW + u]     + Gf;
            float xg = g0[b * GWP + 2 * HW + u] + g1[b * GWP + 2 * HW + u] + Gg;
            float xo = g0[b * GWP + 3 * HW + u] + g1[b * GWP + 3 * HW + u] + Go;
            float cv = sigf(xf) * csm[e] + sigf(xi) * tanhf(xg);
            float hv = sigf(xo) * tanhf(cv);
            csm[e] = cv;
            int ug = j0 + u;
            int ksb = ug >> 3;
            int blk = ((ksb / KsPS) * 4 + (b >> 4)) * KsPS + (ksb % KsPS);
            int P = ((blk * 32 + (b & 7) * 4 + (ug & 3)) << 2)
                    + ((b >> 3) & 1) + (((ug >> 2) & 1) << 1);
            float hr = __uint_as_float(f2tf32(hv));
            g_hbuf[nxt][P] = hr;
            if (outSel == 2)
                Hout[((size_t)b * TT + t) * H + ug] = hv;    // (B,T,H) final out
            else
                Hout[((size_t)t * BB + b) * H + ug] = hv;    // (T,B,H) sequence
            if (saveFinal && t == TT - 1) {
                g_hTp[P] = hr;
                g_cT[b * H + ug] = cv;
            }
        }
        fbar(t + 1);
    }
}

// ---------------- host ----------------
static const int SM512 = 64 + (32 * 512 + 64 * 512 + 2 * 64 * 33 + 64 * 8) * 4;  // 215,616 B
static const int SM256 = 64 + (16 * 256 + 64 * 256 + 2 * 64 * 17 + 64 * 4) * 4;  //  91,712 B

extern "C" void kernel_launch(void* const* d_in, const int* in_sizes, int n_in,
                              void* d_out, int out_size) {
    (void)in_sizes; (void)n_in; (void)out_size;
    const float* x = (const float*)d_in[0];
    const float* p[21];
    for (int i = 0; i < 21; i++) p[i] = (const float*)d_in[i];

    cudaFuncSetAttribute(lstm_rec<512>, cudaFuncAttributeMaxDynamicSharedMemorySize, SM512);
    cudaFuncSetAttribute(lstm_rec<256>, cudaFuncAttributeMaxDynamicSharedMemorySize, SM256);

    dim3 g2048(16, 256), g1024(8, 256);

    // encoder L0: x -> seqA
    gemm_input<<<g2048, 256>>>(0, x, p[1], p[3], p[4], 256, 2048, 0);
    lstm_rec<512><<<64, 512, SM512>>>(p[2], 0, 0, nullptr, 0);
    // encoder L1: seqA -> seqB, save (hT, cT)
    gemm_input<<<g2048, 256>>>(1, x, p[5], p[7], p[8], 512, 2048, 0);
    lstm_rec<512><<<64, 512, SM512>>>(p[6], 0, 1, nullptr, 1);
    // decoder L0: reversed x -> seqA, init from (hT, cT)
    gemm_input<<<g2048, 256>>>(0, x, p[9], p[11], p[12], 256, 2048, 1);
    lstm_rec<512><<<64, 512, SM512>>>(p[10], 1, 0, nullptr, 0);
    // decoder L1: seqA -> seqB
    gemm_input<<<g2048, 256>>>(1, x, p[13], p[15], p[16], 512, 2048, 0);
    lstm_rec<512><<<64, 512, SM512>>>(p[14], 0, 1, nullptr, 0);
    // decoder L2: seqB -> d_out (B,T,256)
    gemm_input<<<g1024, 256>>>(2, x, p[17], p[19], p[20], 512, 1024, 0);
    lstm_rec<256><<<64, 512, SM256>>>(p[18], 0, 2, (float*)d_out, 0);
}